// round 16
// baseline (speedup 1.0000x reference)
#include <cuda_runtime.h>
#include <math_constants.h>
#include <cstdint>

#define DIMC   512
#define HEADS  16
#define HD     32
#define BATCH  8
#define SEQ    1024
#define MTOT   (BATCH*SEQ)   // 8192

// ---------------- scratch (no allocations allowed) ----------------
__device__ float g_qkv[(size_t)MTOT * 3 * DIMC];  // [8192][1536] (tf32-exact)
__device__ float g_y  [(size_t)MTOT * DIMC];      // lepe out (exact fp32)
__device__ float g_xr [(size_t)MTOT * DIMC];      // x rounded to tf32
__device__ float g_yr [(size_t)MTOT * DIMC];      // lepe+attn, tf32-rounded
__device__ float g_wqr[(size_t)3 * DIMC * DIMC];  // w_qkv rounded
__device__ float g_wpr[(size_t)DIMC * DIMC];      // w_proj rounded

// ---------------- helpers ----------------
__device__ __forceinline__ unsigned f2tf(float x) {
    unsigned r; asm("cvt.rna.tf32.f32 %0, %1;" : "=r"(r) : "f"(x)); return r;
}
__device__ __forceinline__ float ex2(float x) {
    float r; asm("ex2.approx.f32 %0, %1;" : "=f"(r) : "f"(x)); return r;
}
__device__ __forceinline__ void mma8(float* c,
                                     unsigned a0, unsigned a1, unsigned a2, unsigned a3,
                                     unsigned b0, unsigned b1) {
    asm volatile("mma.sync.aligned.m16n8k8.row.col.f32.tf32.tf32.f32 "
                 "{%0,%1,%2,%3},{%4,%5,%6,%7},{%8,%9},{%0,%1,%2,%3};"
                 : "+f"(c[0]), "+f"(c[1]), "+f"(c[2]), "+f"(c[3])
                 : "r"(a0), "r"(a1), "r"(a2), "r"(a3), "r"(b0), "r"(b1));
}
__device__ __forceinline__ uint32_t smem_u32(const void* p) {
    uint32_t a;
    asm("{ .reg .u64 t; cvta.to.shared.u64 t, %1; cvt.u32.u64 %0, t; }"
        : "=r"(a) : "l"(p));
    return a;
}
#define CP16(dst, src) \
    asm volatile("cp.async.cg.shared.global [%0], [%1], 16;" \
                 :: "r"(dst), "l"(src) : "memory")
#define CP_COMMIT() asm volatile("cp.async.commit_group;" ::: "memory")
#define CP_WAIT1()  asm volatile("cp.async.wait_group 1;" ::: "memory")
#define CP_WAIT0()  asm volatile("cp.async.wait_group 0;" ::: "memory")

// ============================================================================
// tf32 rounding pass (rna), float4-vectorized
// ============================================================================
__global__ __launch_bounds__(256)
void round_tf32_k(const float* __restrict__ src, float* __restrict__ dst, int n4)
{
    int idx = blockIdx.x * 256 + threadIdx.x;
    if (idx < n4) {
        float4 v = ((const float4*)src)[idx];
        float4 r;
        r.x = __uint_as_float(f2tf(v.x));
        r.y = __uint_as_float(f2tf(v.y));
        r.z = __uint_as_float(f2tf(v.z));
        r.w = __uint_as_float(f2tf(v.w));
        ((float4*)dst)[idx] = r;
    }
}

// ============================================================================
// GEMM (tf32 mma.sync + cp.async, 3-stage pipeline, 1 sync/stage):
// C[M,N] = A[M,K]*B[N,K]^T (+bias).  Inputs MUST be tf32-exact fp32.
// 128x128 CTA, KT=16, 8 warps of 64x32.
// ============================================================================
#define KT 16
#define G_STAGE_W 5120                 // words per stage: A 128*20 + B 128*20
#define G_SMEM    (3 * G_STAGE_W * 4)  // 61440 bytes

__global__ __launch_bounds__(256)
void gemm_tc(const float* __restrict__ A, const float* __restrict__ B,
             float* __restrict__ C, int M, int N, int K,
             const float* __restrict__ bias, int roundOut)
{
    extern __shared__ unsigned sm[];
    const uint32_t sbytes = smem_u32(sm);

    const int tid   = threadIdx.x;
    const int wid   = tid >> 5;
    const int lane  = tid & 31;
    const int g     = lane >> 2;
    const int i     = lane & 3;
    const int mbase = (wid & 1) * 64;
    const int nbase = (wid >> 1) * 32;
    const int m0    = blockIdx.y << 7;
    const int n0    = blockIdx.x << 7;

    const int lrow  = tid >> 1;          // 0..127
    const int lcol  = (tid & 1) << 3;    // 0 or 8
    const float* aptr = A + (size_t)(m0 + lrow) * K + lcol;
    const float* bptr = B + (size_t)(n0 + lrow) * K + lcol;
    const uint32_t dstA = sbytes + (uint32_t)(lrow * 20 + lcol) * 4;
    const uint32_t dstB = dstA + 2560u * 4;

    float c[4][4][4];
#pragma unroll
    for (int mf = 0; mf < 4; mf++)
#pragma unroll
        for (int nf = 0; nf < 4; nf++)
#pragma unroll
            for (int t = 0; t < 4; t++) c[mf][nf][t] = 0.f;

    const int nstages = K / KT;   // 32 for K=512

    auto issue = [&](int s) {
        uint32_t so = (uint32_t)(s % 3) * (G_STAGE_W * 4);
        const float* ap = aptr + s * KT;
        const float* bp = bptr + s * KT;
        CP16(dstA + so,      ap);
        CP16(dstA + so + 16, ap + 4);
        CP16(dstB + so,      bp);
        CP16(dstB + so + 16, bp + 4);
        CP_COMMIT();
    };

    issue(0);
    issue(1);

    for (int s = 0; s < nstages; s++) {
        if (s < nstages - 1) CP_WAIT1(); else CP_WAIT0();
        __syncthreads();
        if (s + 2 < nstages) issue(s + 2);

        const unsigned* As = sm + (s % 3) * G_STAGE_W;
        const unsigned* Bs = As + 2560;

#pragma unroll
        for (int ks = 0; ks < 2; ks++) {
            const int k0i = (ks << 3) + i;
            unsigned a[4][4];
            unsigned b[4][2];
#pragma unroll
            for (int mf = 0; mf < 4; mf++) {
                int r = mbase + (mf << 4);
                a[mf][0] = As[(r + g    ) * 20 + k0i];
                a[mf][1] = As[(r + g + 8) * 20 + k0i];
                a[mf][2] = As[(r + g    ) * 20 + k0i + 4];
                a[mf][3] = As[(r + g + 8) * 20 + k0i + 4];
            }
#pragma unroll
            for (int nf = 0; nf < 4; nf++) {
                int r = nbase + (nf << 3) + g;
                b[nf][0] = Bs[r * 20 + k0i];
                b[nf][1] = Bs[r * 20 + k0i + 4];
            }
#pragma unroll
            for (int mf = 0; mf < 4; mf++)
#pragma unroll
                for (int nf = 0; nf < 4; nf++)
                    mma8(c[mf][nf], a[mf][0], a[mf][1], a[mf][2], a[mf][3],
                                    b[nf][0], b[nf][1]);
        }
    }

    // epilogue
#pragma unroll
    for (int mf = 0; mf < 4; mf++) {
        int r0 = m0 + mbase + (mf << 4) + g;
        int r1 = r0 + 8;
#pragma unroll
        for (int nf = 0; nf < 4; nf++) {
            int col = n0 + nbase + (nf << 3) + (i << 1);
            float v0 = c[mf][nf][0], v1 = c[mf][nf][1];
            float v2 = c[mf][nf][2], v3 = c[mf][nf][3];
            if (bias) {
                float bx = bias[col], by = bias[col + 1];
                v0 += bx; v1 += by; v2 += bx; v3 += by;
            }
            if (roundOut) {
                v0 = __uint_as_float(f2tf(v0)); v1 = __uint_as_float(f2tf(v1));
                v2 = __uint_as_float(f2tf(v2)); v3 = __uint_as_float(f2tf(v3));
            }
            *(float2*)&C[(size_t)r0 * N + col] = make_float2(v0, v1);
            *(float2*)&C[(size_t)r1 * N + col] = make_float2(v2, v3);
        }
    }
}

// ============================================================================
// LePE depthwise 5x5 conv, smem-tiled (exact fp32) -> g_y.
// ============================================================================
__global__ __launch_bounds__(256)
void lepe_conv(const float* __restrict__ x, const float* __restrict__ w,
               const float* __restrict__ bias, float* __restrict__ y)
{
    __shared__ float xs[5][32][64];

    const int c  = threadIdx.x & 63;
    const int jt = threadIdx.x >> 6;
    const int cg = blockIdx.x;
    const int i  = blockIdx.y;
    const int b  = blockIdx.z;
    const int cc = cg * 64 + c;

#pragma unroll
    for (int r = 0; r < 5; r++) {
        int ii = i + r - 2;
        bool ok = (ii >= 0 && ii < 32);
        const float* src = x + ((size_t)((b * 32 + ii) * 32)) * DIMC + cc;
#pragma unroll
        for (int l = 0; l < 8; l++) {
            int jj = jt + (l << 2);
            xs[r][jj][c] = ok ? src[(size_t)jj * DIMC] : 0.f;
        }
    }

    float wr[25];
#pragma unroll
    for (int t = 0; t < 25; t++) wr[t] = w[cc * 25 + t];
    const float bv = bias[cc];

    __syncthreads();

#pragma unroll
    for (int l = 0; l < 8; l++) {
        int jj = jt + (l << 2);
        float acc = bv;
#pragma unroll
        for (int u = 0; u < 5; u++)
#pragma unroll
            for (int v = 0; v < 5; v++) {
                int jv = jj + v - 2;
                if (jv >= 0 && jv < 32)
                    acc += xs[u][jv][c] * wr[u * 5 + v];
            }
        y[((size_t)(b * 1024 + i * 32 + jj)) * DIMC + cc] = acc;
    }
}

// ============================================================================
// Attention (tf32 flash, no-max softmax, deferred row sums).
// CTA = 128 q-rows x (head, batch), 8 warps.  qkv must be tf32-exact.
// p = 2^(q_scaled . k)  with log2(e)*scale folded into Q.  Safe: |logit|<~10.
// Writes yr = tf32-round(y_lepe + attn_out)  (fuses the y rounding pass).
// ============================================================================
#define QB 128
#define KB 32
#define NT (SEQ / KB)   // 32

__global__ __launch_bounds__(256)
void attn_tc(const float* __restrict__ qkv, const float* __restrict__ y,
             float* __restrict__ yr)
{
    __shared__ __align__(16) unsigned Ks[3][KB][36];
    __shared__ __align__(16) unsigned Vs[3][KB][36];
    __shared__ __align__(16) unsigned Ps[QB][36];

    const int tid  = threadIdx.x;
    const int warp = tid >> 5;
    const int lane = tid & 31;
    const int g    = lane >> 2;
    const int i    = lane & 3;
    const int w16  = warp << 4;

    const int qb0 = blockIdx.x * QB;
    const int h   = blockIdx.y;
    const int b   = blockIdx.z;
    // scale * log2(e):  p = 2^(s)
    const float qsc = 0.17677669529663687f * 1.4426950408889634f;

    const size_t rowstride = 3 * DIMC;
    const size_t base  = (size_t)b * SEQ * rowstride + h * HD;
    const size_t kbase = base + DIMC;
    const size_t vbase = base + 2 * DIMC;

    // ---- Q fragments straight from gmem ----
    unsigned qa[4][4];
    {
        const float* q0 = qkv + base + (size_t)(qb0 + w16 + g) * rowstride;
        const float* q1 = q0 + 8 * rowstride;
#pragma unroll
        for (int ks = 0; ks < 4; ks++) {
            int kc = (ks << 3) + i;
            qa[ks][0] = f2tf(q0[kc]     * qsc);
            qa[ks][1] = f2tf(q1[kc]     * qsc);
            qa[ks][2] = f2tf(q0[kc + 4] * qsc);
            qa[ks][3] = f2tf(q1[kc + 4] * qsc);
        }
    }

    // K/V loader: one float4 of K and one of V per thread per tile (cp.async)
    const int lr = tid >> 3;            // 0..31
    const int ld = (tid & 7) << 2;      // 0,4,..,28
    const float* kp = qkv + kbase + (size_t)lr * rowstride + ld;
    const float* vp = qkv + vbase + (size_t)lr * rowstride + ld;

    auto issue = [&](int t) {
        int st = t % 3;
        size_t off = (size_t)t * KB * rowstride;
        CP16(smem_u32(&Ks[st][lr][ld]), kp + off);
        CP16(smem_u32(&Vs[st][lr][ld]), vp + off);
        CP_COMMIT();
    };

    issue(0);
    issue(1);

    float o[4][4];
#pragma unroll
    for (int nf = 0; nf < 4; nf++)
#pragma unroll
        for (int t = 0; t < 4; t++) o[nf][t] = 0.f;
    float l0r = 0.f, l1r = 0.f;   // per-thread partial row sums (8 cols each)

    for (int kt = 0; kt < NT; kt++) {
        const int cur = kt % 3;
        if (kt < NT - 1) CP_WAIT1(); else CP_WAIT0();
        __syncthreads();
        if (kt + 2 < NT) issue(kt + 2);

        // ---- S = Qs K^T  (s in log2 domain) ----
        float s[4][4];
#pragma unroll
        for (int nf = 0; nf < 4; nf++) {
            s[nf][0] = 0.f; s[nf][1] = 0.f; s[nf][2] = 0.f; s[nf][3] = 0.f;
        }
#pragma unroll
        for (int nf = 0; nf < 4; nf++) {
            int nr = (nf << 3) + g;
#pragma unroll
            for (int ks = 0; ks < 4; ks++) {
                int kc = (ks << 3) + i;
                mma8(s[nf], qa[ks][0], qa[ks][1], qa[ks][2], qa[ks][3],
                     Ks[cur][nr][kc], Ks[cur][nr][kc + 4]);
            }
        }

        // ---- p = 2^s, accumulate partial sums, stage P as tf32 ----
#pragma unroll
        for (int nf = 0; nf < 4; nf++) {
            float p0 = ex2(s[nf][0]);
            float p1 = ex2(s[nf][1]);
            float p2 = ex2(s[nf][2]);
            float p3 = ex2(s[nf][3]);
            l0r += p0 + p1;
            l1r += p2 + p3;
            int col = (nf << 3) + (i << 1);
            *(uint2*)&Ps[w16 + g    ][col] = make_uint2(f2tf(p0), f2tf(p1));
            *(uint2*)&Ps[w16 + g + 8][col] = make_uint2(f2tf(p2), f2tf(p3));
        }
        __syncwarp();   // own-warp Ps rows visible

        // ---- O += P * V ----
#pragma unroll
        for (int ks = 0; ks < 4; ks++) {
            int kc = (ks << 3) + i;
            unsigned pa0 = Ps[w16 + g    ][kc];
            unsigned pa1 = Ps[w16 + g + 8][kc];
            unsigned pa2 = Ps[w16 + g    ][kc + 4];
            unsigned pa3 = Ps[w16 + g + 8][kc + 4];
#pragma unroll
            for (int nf = 0; nf < 4; nf++) {
                int nc = (nf << 3) + g;
                mma8(o[nf], pa0, pa1, pa2, pa3,
                     Vs[cur][kc][nc], Vs[cur][kc + 4][nc]);
            }
        }
    }

    // ---- finalize: row sums (2 shuffles total), yr = round(y + O/l) ----
    l0r += __shfl_xor_sync(0xffffffffu, l0r, 1);
    l0r += __shfl_xor_sync(0xffffffffu, l0r, 2);
    l1r += __shfl_xor_sync(0xffffffffu, l1r, 1);
    l1r += __shfl_xor_sync(0xffffffffu, l1r, 2);
    float inv0 = 1.f / l0r;
    float inv1 = 1.f / l1r;
    int r0 = b * SEQ + qb0 + w16 + g;
    int r1 = r0 + 8;
#pragma unroll
    for (int nf = 0; nf < 4; nf++) {
        int col = h * HD + (nf << 3) + (i << 1);
        size_t i00 = (size_t)r0 * DIMC + col;
        size_t i10 = (size_t)r1 * DIMC + col;
        yr[i00]     = __uint_as_float(f2tf(y[i00]     + o[nf][0] * inv0));
        yr[i00 + 1] = __uint_as_float(f2tf(y[i00 + 1] + o[nf][1] * inv0));
        yr[i10]     = __uint_as_float(f2tf(y[i10]     + o[nf][2] * inv1));
        yr[i10 + 1] = __uint_as_float(f2tf(y[i10 + 1] + o[nf][3] * inv1));
    }
}

// ============================================================================
// launch
// ============================================================================
extern "C" void kernel_launch(void* const* d_in, const int* in_sizes, int n_in,
                              void* d_out, int out_size)
{
    const float* x      = (const float*)d_in[0];
    const float* w_qkv  = (const float*)d_in[1];
    const float* w_proj = (const float*)d_in[2];
    const float* b_proj = (const float*)d_in[3];
    const float* w_lepe = (const float*)d_in[4];
    const float* b_lepe = (const float*)d_in[5];
    float* out = (float*)d_out;

    void *p_qkv, *p_y, *p_xr, *p_yr, *p_wqr, *p_wpr;
    cudaGetSymbolAddress(&p_qkv, g_qkv);
    cudaGetSymbolAddress(&p_y,   g_y);
    cudaGetSymbolAddress(&p_xr,  g_xr);
    cudaGetSymbolAddress(&p_yr,  g_yr);
    cudaGetSymbolAddress(&p_wqr, g_wqr);
    cudaGetSymbolAddress(&p_wpr, g_wpr);
    float* qkv = (float*)p_qkv;
    float* y   = (float*)p_y;
    float* xr  = (float*)p_xr;
    float* yr  = (float*)p_yr;
    float* wqr = (float*)p_wqr;
    float* wpr = (float*)p_wpr;

    cudaFuncSetAttribute(gemm_tc, cudaFuncAttributeMaxDynamicSharedMemorySize,
                         G_SMEM);

    // 0) round inputs to tf32 (rna) once
    {
        int n4x = MTOT * DIMC / 4;
        int n4q = 3 * DIMC * DIMC / 4;
        int n4p = DIMC * DIMC / 4;
        round_tf32_k<<<(n4x + 255) / 256, 256>>>(x,      xr,  n4x);
        round_tf32_k<<<(n4q + 255) / 256, 256>>>(w_qkv,  wqr, n4q);
        round_tf32_k<<<(n4p + 255) / 256, 256>>>(w_proj, wpr, n4p);
    }

    // 1) QKV GEMM (tf32-exact output for attention)
    gemm_tc<<<dim3(3 * DIMC / 128, MTOT / 128), 256, G_SMEM>>>(
        xr, wqr, qkv, MTOT, 3 * DIMC, DIMC, nullptr, 1);
    // 2) LePE conv -> y (exact fp32)
    lepe_conv<<<dim3(8, 32, BATCH), 256>>>(x, w_lepe, b_lepe, y);
    // 3) attention: yr = round(y + attn)   (fused rounding)
    attn_tc<<<dim3(SEQ / QB, HEADS, BATCH), 256>>>(qkv, y, yr);
    // 4) proj: out = yr @ wpr^T + b_proj
    gemm_tc<<<dim3(DIMC / 128, MTOT / 128), 256, G_SMEM>>>(
        yr, wpr, out, MTOT, DIMC, DIMC, b_proj, 0);
}

// round 17
// speedup vs baseline: 1.0170x; 1.0170x over previous
#include <cuda_runtime.h>
#include <math_constants.h>
#include <cstdint>

#define DIMC   512
#define HEADS  16
#define HD     32
#define BATCH  8
#define SEQ    1024
#define MTOT   (BATCH*SEQ)   // 8192

// ---------------- scratch (no allocations allowed) ----------------
__device__ float g_qkv[(size_t)MTOT * 3 * DIMC];  // [8192][1536] (tf32-exact)
__device__ float g_y  [(size_t)MTOT * DIMC];      // lepe out (exact fp32)
__device__ float g_xr [(size_t)MTOT * DIMC];      // x rounded to tf32
__device__ float g_yr [(size_t)MTOT * DIMC];      // lepe+attn, tf32-rounded
__device__ float g_wqr[(size_t)3 * DIMC * DIMC];  // w_qkv rounded
__device__ float g_wpr[(size_t)DIMC * DIMC];      // w_proj rounded

// ---------------- helpers ----------------
__device__ __forceinline__ unsigned f2tf(float x) {
    unsigned r; asm("cvt.rna.tf32.f32 %0, %1;" : "=r"(r) : "f"(x)); return r;
}
__device__ __forceinline__ float ex2(float x) {
    float r; asm("ex2.approx.f32 %0, %1;" : "=f"(r) : "f"(x)); return r;
}
__device__ __forceinline__ void mma8(float* c,
                                     unsigned a0, unsigned a1, unsigned a2, unsigned a3,
                                     unsigned b0, unsigned b1) {
    asm volatile("mma.sync.aligned.m16n8k8.row.col.f32.tf32.tf32.f32 "
                 "{%0,%1,%2,%3},{%4,%5,%6,%7},{%8,%9},{%0,%1,%2,%3};"
                 : "+f"(c[0]), "+f"(c[1]), "+f"(c[2]), "+f"(c[3])
                 : "r"(a0), "r"(a1), "r"(a2), "r"(a3), "r"(b0), "r"(b1));
}
__device__ __forceinline__ uint32_t smem_u32(const void* p) {
    uint32_t a;
    asm("{ .reg .u64 t; cvta.to.shared.u64 t, %1; cvt.u32.u64 %0, t; }"
        : "=r"(a) : "l"(p));
    return a;
}
#define CP16(dst, src) \
    asm volatile("cp.async.cg.shared.global [%0], [%1], 16;" \
                 :: "r"(dst), "l"(src) : "memory")
#define CP_COMMIT() asm volatile("cp.async.commit_group;" ::: "memory")
#define CP_WAIT1()  asm volatile("cp.async.wait_group 1;" ::: "memory")
#define CP_WAIT0()  asm volatile("cp.async.wait_group 0;" ::: "memory")

// ============================================================================
// tf32 rounding pass (rna), float4-vectorized
// ============================================================================
__global__ __launch_bounds__(256)
void round_tf32_k(const float* __restrict__ src, float* __restrict__ dst, int n4)
{
    int idx = blockIdx.x * 256 + threadIdx.x;
    if (idx < n4) {
        float4 v = ((const float4*)src)[idx];
        float4 r;
        r.x = __uint_as_float(f2tf(v.x));
        r.y = __uint_as_float(f2tf(v.y));
        r.z = __uint_as_float(f2tf(v.z));
        r.w = __uint_as_float(f2tf(v.w));
        ((float4*)dst)[idx] = r;
    }
}

// ============================================================================
// GEMM (tf32 mma.sync + cp.async, 3-stage pipeline, 1 sync/stage):
// C[M,N] = A[M,K]*B[N,K]^T (+bias).  Inputs MUST be tf32-exact fp32.
// 128x128 CTA, KT=16, 8 warps of 64x32.
// ============================================================================
#define KT 16
#define G_STAGE_W 5120                 // words per stage: A 128*20 + B 128*20
#define G_SMEM    (3 * G_STAGE_W * 4)  // 61440 bytes

__global__ __launch_bounds__(256)
void gemm_tc(const float* __restrict__ A, const float* __restrict__ B,
             float* __restrict__ C, int M, int N, int K,
             const float* __restrict__ bias, int roundOut)
{
    extern __shared__ unsigned sm[];
    const uint32_t sbytes = smem_u32(sm);

    const int tid   = threadIdx.x;
    const int wid   = tid >> 5;
    const int lane  = tid & 31;
    const int g     = lane >> 2;
    const int i     = lane & 3;
    const int mbase = (wid & 1) * 64;
    const int nbase = (wid >> 1) * 32;
    const int m0    = blockIdx.y << 7;
    const int n0    = blockIdx.x << 7;

    const int lrow  = tid >> 1;          // 0..127
    const int lcol  = (tid & 1) << 3;    // 0 or 8
    const float* aptr = A + (size_t)(m0 + lrow) * K + lcol;
    const float* bptr = B + (size_t)(n0 + lrow) * K + lcol;
    const uint32_t dstA = sbytes + (uint32_t)(lrow * 20 + lcol) * 4;
    const uint32_t dstB = dstA + 2560u * 4;

    float c[4][4][4];
#pragma unroll
    for (int mf = 0; mf < 4; mf++)
#pragma unroll
        for (int nf = 0; nf < 4; nf++)
#pragma unroll
            for (int t = 0; t < 4; t++) c[mf][nf][t] = 0.f;

    const int nstages = K / KT;   // 32 for K=512

    auto issue = [&](int s) {
        uint32_t so = (uint32_t)(s % 3) * (G_STAGE_W * 4);
        const float* ap = aptr + s * KT;
        const float* bp = bptr + s * KT;
        CP16(dstA + so,      ap);
        CP16(dstA + so + 16, ap + 4);
        CP16(dstB + so,      bp);
        CP16(dstB + so + 16, bp + 4);
        CP_COMMIT();
    };

    issue(0);
    issue(1);

    for (int s = 0; s < nstages; s++) {
        if (s < nstages - 1) CP_WAIT1(); else CP_WAIT0();
        __syncthreads();
        if (s + 2 < nstages) issue(s + 2);

        const unsigned* As = sm + (s % 3) * G_STAGE_W;
        const unsigned* Bs = As + 2560;

#pragma unroll
        for (int ks = 0; ks < 2; ks++) {
            const int k0i = (ks << 3) + i;
            unsigned a[4][4];
            unsigned b[4][2];
#pragma unroll
            for (int mf = 0; mf < 4; mf++) {
                int r = mbase + (mf << 4);
                a[mf][0] = As[(r + g    ) * 20 + k0i];
                a[mf][1] = As[(r + g + 8) * 20 + k0i];
                a[mf][2] = As[(r + g    ) * 20 + k0i + 4];
                a[mf][3] = As[(r + g + 8) * 20 + k0i + 4];
            }
#pragma unroll
            for (int nf = 0; nf < 4; nf++) {
                int r = nbase + (nf << 3) + g;
                b[nf][0] = Bs[r * 20 + k0i];
                b[nf][1] = Bs[r * 20 + k0i + 4];
            }
#pragma unroll
            for (int mf = 0; mf < 4; mf++)
#pragma unroll
                for (int nf = 0; nf < 4; nf++)
                    mma8(c[mf][nf], a[mf][0], a[mf][1], a[mf][2], a[mf][3],
                                    b[nf][0], b[nf][1]);
        }
    }

    // epilogue
#pragma unroll
    for (int mf = 0; mf < 4; mf++) {
        int r0 = m0 + mbase + (mf << 4) + g;
        int r1 = r0 + 8;
#pragma unroll
        for (int nf = 0; nf < 4; nf++) {
            int col = n0 + nbase + (nf << 3) + (i << 1);
            float v0 = c[mf][nf][0], v1 = c[mf][nf][1];
            float v2 = c[mf][nf][2], v3 = c[mf][nf][3];
            if (bias) {
                float bx = bias[col], by = bias[col + 1];
                v0 += bx; v1 += by; v2 += bx; v3 += by;
            }
            if (roundOut) {
                v0 = __uint_as_float(f2tf(v0)); v1 = __uint_as_float(f2tf(v1));
                v2 = __uint_as_float(f2tf(v2)); v3 = __uint_as_float(f2tf(v3));
            }
            *(float2*)&C[(size_t)r0 * N + col] = make_float2(v0, v1);
            *(float2*)&C[(size_t)r1 * N + col] = make_float2(v2, v3);
        }
    }
}

// ============================================================================
// LePE depthwise 5x5 conv, smem-tiled (exact fp32) -> g_y.
// ============================================================================
__global__ __launch_bounds__(256)
void lepe_conv(const float* __restrict__ x, const float* __restrict__ w,
               const float* __restrict__ bias, float* __restrict__ y)
{
    __shared__ float xs[5][32][64];

    const int c  = threadIdx.x & 63;
    const int jt = threadIdx.x >> 6;
    const int cg = blockIdx.x;
    const int i  = blockIdx.y;
    const int b  = blockIdx.z;
    const int cc = cg * 64 + c;

#pragma unroll
    for (int r = 0; r < 5; r++) {
        int ii = i + r - 2;
        bool ok = (ii >= 0 && ii < 32);
        const float* src = x + ((size_t)((b * 32 + ii) * 32)) * DIMC + cc;
#pragma unroll
        for (int l = 0; l < 8; l++) {
            int jj = jt + (l << 2);
            xs[r][jj][c] = ok ? src[(size_t)jj * DIMC] : 0.f;
        }
    }

    float wr[25];
#pragma unroll
    for (int t = 0; t < 25; t++) wr[t] = w[cc * 25 + t];
    const float bv = bias[cc];

    __syncthreads();

#pragma unroll
    for (int l = 0; l < 8; l++) {
        int jj = jt + (l << 2);
        float acc = bv;
#pragma unroll
        for (int u = 0; u < 5; u++)
#pragma unroll
            for (int v = 0; v < 5; v++) {
                int jv = jj + v - 2;
                if (jv >= 0 && jv < 32)
                    acc += xs[u][jv][c] * wr[u * 5 + v];
            }
        y[((size_t)(b * 1024 + i * 32 + jj)) * DIMC + cc] = acc;
    }
}

// ============================================================================
// Attention (tf32 flash, no-max softmax, deferred row sums).
// CTA = 128 q-rows x (head, batch), 8 warps.  qkv must be tf32-exact.
// p = 2^(q_scaled . k)  with log2(e)*scale folded into Q.  Safe: |logit|<~15.
// Ps stores RAW fp32 p bits (MMA truncates to tf32 internally; ~6e-5 bias).
// Writes yr = tf32-round(y_lepe + attn_out)  (fuses the y rounding pass).
// ============================================================================
#define QB 128
#define KB 32
#define NT (SEQ / KB)   // 32

__global__ __launch_bounds__(256)
void attn_tc(const float* __restrict__ qkv, const float* __restrict__ y,
             float* __restrict__ yr)
{
    __shared__ __align__(16) unsigned Ks[3][KB][36];
    __shared__ __align__(16) unsigned Vs[3][KB][36];
    __shared__ __align__(16) unsigned Ps[QB][36];

    const int tid  = threadIdx.x;
    const int warp = tid >> 5;
    const int lane = tid & 31;
    const int g    = lane >> 2;
    const int i    = lane & 3;
    const int w16  = warp << 4;

    const int qb0 = blockIdx.x * QB;
    const int h   = blockIdx.y;
    const int b   = blockIdx.z;
    // scale * log2(e):  p = 2^(s)
    const float qsc = 0.17677669529663687f * 1.4426950408889634f;

    const size_t rowstride = 3 * DIMC;
    const size_t base  = (size_t)b * SEQ * rowstride + h * HD;
    const size_t kbase = base + DIMC;
    const size_t vbase = base + 2 * DIMC;

    // ---- Q fragments straight from gmem ----
    unsigned qa[4][4];
    {
        const float* q0 = qkv + base + (size_t)(qb0 + w16 + g) * rowstride;
        const float* q1 = q0 + 8 * rowstride;
#pragma unroll
        for (int ks = 0; ks < 4; ks++) {
            int kc = (ks << 3) + i;
            qa[ks][0] = f2tf(q0[kc]     * qsc);
            qa[ks][1] = f2tf(q1[kc]     * qsc);
            qa[ks][2] = f2tf(q0[kc + 4] * qsc);
            qa[ks][3] = f2tf(q1[kc + 4] * qsc);
        }
    }

    // K/V loader: one float4 of K and one of V per thread per tile (cp.async)
    const int lr = tid >> 3;            // 0..31
    const int ld = (tid & 7) << 2;      // 0,4,..,28
    const float* kp = qkv + kbase + (size_t)lr * rowstride + ld;
    const float* vp = qkv + vbase + (size_t)lr * rowstride + ld;

    auto issue = [&](int t) {
        int st = t % 3;
        size_t off = (size_t)t * KB * rowstride;
        CP16(smem_u32(&Ks[st][lr][ld]), kp + off);
        CP16(smem_u32(&Vs[st][lr][ld]), vp + off);
        CP_COMMIT();
    };

    issue(0);
    issue(1);

    float o[4][4];
#pragma unroll
    for (int nf = 0; nf < 4; nf++)
#pragma unroll
        for (int t = 0; t < 4; t++) o[nf][t] = 0.f;
    float l0r = 0.f, l1r = 0.f;   // per-thread partial row sums (8 cols each)

    for (int kt = 0; kt < NT; kt++) {
        const int cur = kt % 3;
        if (kt < NT - 1) CP_WAIT1(); else CP_WAIT0();
        __syncthreads();
        if (kt + 2 < NT) issue(kt + 2);

        // ---- S = Qs K^T  (s in log2 domain) ----
        float s[4][4];
#pragma unroll
        for (int nf = 0; nf < 4; nf++) {
            s[nf][0] = 0.f; s[nf][1] = 0.f; s[nf][2] = 0.f; s[nf][3] = 0.f;
        }
#pragma unroll
        for (int nf = 0; nf < 4; nf++) {
            int nr = (nf << 3) + g;
#pragma unroll
            for (int ks = 0; ks < 4; ks++) {
                int kc = (ks << 3) + i;
                mma8(s[nf], qa[ks][0], qa[ks][1], qa[ks][2], qa[ks][3],
                     Ks[cur][nr][kc], Ks[cur][nr][kc + 4]);
            }
        }

        // ---- p = 2^s, accumulate partial sums, stage raw p bits ----
#pragma unroll
        for (int nf = 0; nf < 4; nf++) {
            float p0 = ex2(s[nf][0]);
            float p1 = ex2(s[nf][1]);
            float p2 = ex2(s[nf][2]);
            float p3 = ex2(s[nf][3]);
            l0r += p0 + p1;
            l1r += p2 + p3;
            int col = (nf << 3) + (i << 1);
            *(uint2*)&Ps[w16 + g    ][col] =
                make_uint2(__float_as_uint(p0), __float_as_uint(p1));
            *(uint2*)&Ps[w16 + g + 8][col] =
                make_uint2(__float_as_uint(p2), __float_as_uint(p3));
        }
        __syncwarp();   // own-warp Ps rows visible

        // ---- O += P * V ----
#pragma unroll
        for (int ks = 0; ks < 4; ks++) {
            int kc = (ks << 3) + i;
            unsigned pa0 = Ps[w16 + g    ][kc];
            unsigned pa1 = Ps[w16 + g + 8][kc];
            unsigned pa2 = Ps[w16 + g    ][kc + 4];
            unsigned pa3 = Ps[w16 + g + 8][kc + 4];
#pragma unroll
            for (int nf = 0; nf < 4; nf++) {
                int nc = (nf << 3) + g;
                mma8(o[nf], pa0, pa1, pa2, pa3,
                     Vs[cur][kc][nc], Vs[cur][kc + 4][nc]);
            }
        }
    }

    // ---- finalize: row sums (2 shuffles per half), yr = round(y + O/l) ----
    l0r += __shfl_xor_sync(0xffffffffu, l0r, 1);
    l0r += __shfl_xor_sync(0xffffffffu, l0r, 2);
    l1r += __shfl_xor_sync(0xffffffffu, l1r, 1);
    l1r += __shfl_xor_sync(0xffffffffu, l1r, 2);
    float inv0 = 1.f / l0r;
    float inv1 = 1.f / l1r;
    int r0 = b * SEQ + qb0 + w16 + g;
    int r1 = r0 + 8;
#pragma unroll
    for (int nf = 0; nf < 4; nf++) {
        int col = h * HD + (nf << 3) + (i << 1);
        size_t i00 = (size_t)r0 * DIMC + col;
        size_t i10 = (size_t)r1 * DIMC + col;
        yr[i00]     = __uint_as_float(f2tf(y[i00]     + o[nf][0] * inv0));
        yr[i00 + 1] = __uint_as_float(f2tf(y[i00 + 1] + o[nf][1] * inv0));
        yr[i10]     = __uint_as_float(f2tf(y[i10]     + o[nf][2] * inv1));
        yr[i10 + 1] = __uint_as_float(f2tf(y[i10 + 1] + o[nf][3] * inv1));
    }
}

// ============================================================================
// launch
// ============================================================================
extern "C" void kernel_launch(void* const* d_in, const int* in_sizes, int n_in,
                              void* d_out, int out_size)
{
    const float* x      = (const float*)d_in[0];
    const float* w_qkv  = (const float*)d_in[1];
    const float* w_proj = (const float*)d_in[2];
    const float* b_proj = (const float*)d_in[3];
    const float* w_lepe = (const float*)d_in[4];
    const float* b_lepe = (const float*)d_in[5];
    float* out = (float*)d_out;

    void *p_qkv, *p_y, *p_xr, *p_yr, *p_wqr, *p_wpr;
    cudaGetSymbolAddress(&p_qkv, g_qkv);
    cudaGetSymbolAddress(&p_y,   g_y);
    cudaGetSymbolAddress(&p_xr,  g_xr);
    cudaGetSymbolAddress(&p_yr,  g_yr);
    cudaGetSymbolAddress(&p_wqr, g_wqr);
    cudaGetSymbolAddress(&p_wpr, g_wpr);
    float* qkv = (float*)p_qkv;
    float* y   = (float*)p_y;
    float* xr  = (float*)p_xr;
    float* yr  = (float*)p_yr;
    float* wqr = (float*)p_wqr;
    float* wpr = (float*)p_wpr;

    cudaFuncSetAttribute(gemm_tc, cudaFuncAttributeMaxDynamicSharedMemorySize,
                         G_SMEM);

    // 0) round inputs to tf32 (rna) once
    {
        int n4x = MTOT * DIMC / 4;
        int n4q = 3 * DIMC * DIMC / 4;
        int n4p = DIMC * DIMC / 4;
        round_tf32_k<<<(n4x + 255) / 256, 256>>>(x,      xr,  n4x);
        round_tf32_k<<<(n4q + 255) / 256, 256>>>(w_qkv,  wqr, n4q);
        round_tf32_k<<<(n4p + 255) / 256, 256>>>(w_proj, wpr, n4p);
    }

    // 1) QKV GEMM (tf32-exact output for attention)
    gemm_tc<<<dim3(3 * DIMC / 128, MTOT / 128), 256, G_SMEM>>>(
        xr, wqr, qkv, MTOT, 3 * DIMC, DIMC, nullptr, 1);
    // 2) LePE conv -> y (exact fp32)
    lepe_conv<<<dim3(8, 32, BATCH), 256>>>(x, w_lepe, b_lepe, y);
    // 3) attention: yr = round(y + attn)   (fused rounding)
    attn_tc<<<dim3(SEQ / QB, HEADS, BATCH), 256>>>(qkv, y, yr);
    // 4) proj: out = yr @ wpr^T + b_proj
    gemm_tc<<<dim3(DIMC / 128, MTOT / 128), 256, G_SMEM>>>(
        yr, wpr, out, MTOT, DIMC, DIMC, b_proj, 0);
}